// round 1
// baseline (speedup 1.0000x reference)
#include <cuda_runtime.h>
#include <math.h>

#define BATCH 2
#define SEQ   2048
#define CDIM  2048
#define NH    16
#define NKV   4
#define HD    128
#define KVC   (NKV*HD)   // 512
#define GRP   (NH/NKV)   // 4

// Scratch (no cudaMalloc allowed): q, k, v post-projection(+RoPE), attention out
__device__ float g_q[BATCH*SEQ*CDIM];
__device__ float g_k[BATCH*SEQ*KVC];
__device__ float g_v[BATCH*SEQ*KVC];
__device__ float g_attn[BATCH*SEQ*CDIM];

// ---------------------------------------------------------------------------
// SGEMM:  C[M,N] = A[M,K] @ B[K,N] + bias[N]   (all row-major, tiles divide)
// 128x64 block tile, BK=16, 256 threads, 8x4 micro-tile per thread.
// ---------------------------------------------------------------------------
#define BM 128
#define BN 64
#define BK 16

__global__ __launch_bounds__(256) void sgemm_bias(
    const float* __restrict__ A, const float* __restrict__ Bm,
    const float* __restrict__ bias, float* __restrict__ Cm,
    int M, int Nd, int K)
{
    __shared__ float As[BK*BM];   // transposed: As[k*BM + m]
    __shared__ float Bs[BK*BN];   // Bs[k*BN + n]

    const int tid = threadIdx.x;
    const int m0 = blockIdx.y * BM;
    const int n0 = blockIdx.x * BN;
    const int ty = tid >> 4;      // 0..15 -> 8 rows each
    const int tx = tid & 15;      // 0..15 -> 4 cols each

    float acc[8][4];
    #pragma unroll
    for (int i = 0; i < 8; i++)
        #pragma unroll
        for (int j = 0; j < 4; j++) acc[i][j] = 0.f;

    const int brow = tid >> 4;    // 0..15
    const int bc4  = tid & 15;    // 0..15

    for (int kt = 0; kt < K; kt += BK) {
        // A tile: 128x16 = 512 float4 chunks, 2 per thread, stored transposed
        #pragma unroll
        for (int u = 0; u < 2; u++) {
            int f = tid + u * 256;
            int row = f >> 2, c4 = f & 3;
            float4 av = *(const float4*)&A[(size_t)(m0 + row) * K + kt + c4 * 4];
            As[(c4*4 + 0)*BM + row] = av.x;
            As[(c4*4 + 1)*BM + row] = av.y;
            As[(c4*4 + 2)*BM + row] = av.z;
            As[(c4*4 + 3)*BM + row] = av.w;
        }
        // B tile: 16x64 = 256 float4, 1 per thread
        {
            float4 bv = *(const float4*)&Bm[(size_t)(kt + brow) * Nd + n0 + bc4 * 4];
            *(float4*)&Bs[brow*BN + bc4*4] = bv;
        }
        __syncthreads();

        #pragma unroll
        for (int kk = 0; kk < BK; kk++) {
            float4 a0 = *(const float4*)&As[kk*BM + ty*8];
            float4 a1 = *(const float4*)&As[kk*BM + ty*8 + 4];
            float4 b0 = *(const float4*)&Bs[kk*BN + tx*4];
            float av8[8] = {a0.x, a0.y, a0.z, a0.w, a1.x, a1.y, a1.z, a1.w};
            float bv4[4] = {b0.x, b0.y, b0.z, b0.w};
            #pragma unroll
            for (int i = 0; i < 8; i++)
                #pragma unroll
                for (int j = 0; j < 4; j++)
                    acc[i][j] += av8[i] * bv4[j];
        }
        __syncthreads();
    }

    float4 bb = make_float4(0.f, 0.f, 0.f, 0.f);
    if (bias) bb = *(const float4*)&bias[n0 + tx*4];
    #pragma unroll
    for (int i = 0; i < 8; i++) {
        float4 r;
        r.x = acc[i][0] + bb.x;
        r.y = acc[i][1] + bb.y;
        r.z = acc[i][2] + bb.z;
        r.w = acc[i][3] + bb.w;
        *(float4*)&Cm[(size_t)(m0 + ty*8 + i) * Nd + n0 + tx*4] = r;
    }
}

// ---------------------------------------------------------------------------
// Interleaved RoPE in place.  buf rows are (b*SEQ+n), row width W (CDIM or KVC),
// each head of HD elems rotated pairwise: (x0,x1) -> (x0*c - x1*s, x1*c + x0*s)
// ---------------------------------------------------------------------------
__global__ void rope_kernel(float* __restrict__ buf, const int* __restrict__ pos_ids,
                            int W, int total_pairs)
{
    int p = blockIdx.x * blockDim.x + threadIdx.x;
    if (p >= total_pairs) return;
    int halfW = W >> 1;
    int row = p / halfW;
    int j = p - row * halfW;
    int i = j & (HD/2 - 1);   // pair index within head, 0..63
    int head = j >> 6;        // HD/2 == 64
    float pos = (float)pos_ids[row];
    // inv_freq = 10000^(-2i/HD)
    float inv = expf(-(2.0f * (float)i / (float)HD) * 9.210340371976184f);
    float ang = pos * inv;
    float s, c;
    sincosf(ang, &s, &c);
    float* x = buf + (size_t)row * W + head * HD + 2 * i;
    float x0 = x[0], x1 = x[1];
    x[0] = x0 * c - x1 * s;
    x[1] = x1 * c + x0 * s;
}

// ---------------------------------------------------------------------------
// Causal GQA flash attention, fp32 SIMT.
// Block = one (b, h, 64-query tile). 256 threads.
// Online softmax with per-row (m, l) state; 64x64 score tiles.
// ---------------------------------------------------------------------------
#define BQ   64
#define BKT  64
#define QSTR 132   // padded stride (floats) for Q/K/V tiles
#define PSTR 68    // padded stride for P tile

__global__ __launch_bounds__(256) void flash_attn(
    const float* __restrict__ q, const float* __restrict__ k,
    const float* __restrict__ v, float* __restrict__ o)
{
    extern __shared__ float sm[];
    float* Qs    = sm;                    // BQ  x QSTR
    float* Ks    = Qs + BQ*QSTR;          // BKT x QSTR
    float* Vs    = Ks + BKT*QSTR;         // BKT x QSTR
    float* Ps    = Vs + BKT*QSTR;         // BQ  x PSTR
    float* row_m = Ps + BQ*PSTR;          // BQ
    float* row_l = row_m + BQ;            // BQ
    float* row_a = row_l + BQ;            // BQ

    const int tid = threadIdx.x;
    const int ty = tid >> 4;   // 0..15: owns score rows ty*4..+3 and O rows ty*4..+3
    const int tx = tid & 15;   // 0..15: score cols tx*4..+3, O cols tx*8..+7
    const int qt = blockIdx.x;
    const int bh = blockIdx.y;
    const int b = bh / NH, h = bh % NH;
    const int kvh = h / GRP;
    const int q0 = qt * BQ;

    // Load Q tile (64 x 128)
    for (int f = tid; f < BQ * 32; f += 256) {
        int row = f >> 5, c4 = f & 31;
        *(float4*)&Qs[row*QSTR + c4*4] =
            *(const float4*)&q[((size_t)(b*SEQ + q0 + row)) * CDIM + h*HD + c4*4];
    }
    if (tid < BQ) { row_m[tid] = -1e30f; row_l[tid] = 0.f; }

    float acc_o[4][8];
    #pragma unroll
    for (int i = 0; i < 4; i++)
        #pragma unroll
        for (int j = 0; j < 8; j++) acc_o[i][j] = 0.f;

    __syncthreads();

    const float scale = 0.08838834764831845f;   // 1/sqrt(128)

    for (int kt = 0; kt <= qt; kt++) {
        const int k0 = kt * BKT;

        // Load K and V tiles (64 x 128 each)
        for (int f = tid; f < BKT * 32; f += 256) {
            int row = f >> 5, c4 = f & 31;
            size_t gofs = ((size_t)(b*SEQ + k0 + row)) * KVC + kvh*HD + c4*4;
            *(float4*)&Ks[row*QSTR + c4*4] = *(const float4*)&k[gofs];
            *(float4*)&Vs[row*QSTR + c4*4] = *(const float4*)&v[gofs];
        }
        __syncthreads();

        // S = Q K^T  (4x4 micro-tile per thread)
        float sacc[4][4];
        #pragma unroll
        for (int i = 0; i < 4; i++)
            #pragma unroll
            for (int j = 0; j < 4; j++) sacc[i][j] = 0.f;

        #pragma unroll 4
        for (int d = 0; d < HD; d += 4) {
            float4 qv[4], kv4[4];
            #pragma unroll
            for (int i = 0; i < 4; i++)
                qv[i] = *(const float4*)&Qs[(ty*4 + i)*QSTR + d];
            #pragma unroll
            for (int j = 0; j < 4; j++)
                kv4[j] = *(const float4*)&Ks[(tx*4 + j)*QSTR + d];
            #pragma unroll
            for (int i = 0; i < 4; i++)
                #pragma unroll
                for (int j = 0; j < 4; j++)
                    sacc[i][j] += qv[i].x*kv4[j].x + qv[i].y*kv4[j].y
                                + qv[i].z*kv4[j].z + qv[i].w*kv4[j].w;
        }

        // Per-row online softmax.  Row r is owned by the 16 lanes sharing ty
        // (one half-warp) -> shfl_xor over offsets 8..1 stays in-group.
        #pragma unroll
        for (int i = 0; i < 4; i++) {
            const int r = ty*4 + i;
            const int rg = q0 + r;
            float p4[4];
            float mx = -1e30f;
            #pragma unroll
            for (int j = 0; j < 4; j++) {
                float sv = sacc[i][j] * scale;
                if (k0 + tx*4 + j > rg) sv = -1e30f;   // causal mask
                sacc[i][j] = sv;
                mx = fmaxf(mx, sv);
            }
            #pragma unroll
            for (int off = 8; off > 0; off >>= 1)
                mx = fmaxf(mx, __shfl_xor_sync(0xffffffffu, mx, off));

            float m_old = row_m[r];
            float m_new = fmaxf(m_old, mx);
            float sum = 0.f;
            #pragma unroll
            for (int j = 0; j < 4; j++) {
                float pv = __expf(sacc[i][j] - m_new);
                p4[j] = pv;
                sum += pv;
            }
            #pragma unroll
            for (int off = 8; off > 0; off >>= 1)
                sum += __shfl_xor_sync(0xffffffffu, sum, off);

            if (tx == 0) {
                float alpha = __expf(m_old - m_new);
                row_a[r] = alpha;
                row_l[r] = row_l[r] * alpha + sum;
                row_m[r] = m_new;
            }
            #pragma unroll
            for (int j = 0; j < 4; j++)
                Ps[r*PSTR + tx*4 + j] = p4[j];
        }
        __syncthreads();

        // O = O*alpha + P @ V   (4 rows x 8 d-cols per thread)
        #pragma unroll
        for (int i = 0; i < 4; i++) {
            float al = row_a[ty*4 + i];
            #pragma unroll
            for (int j = 0; j < 8; j++) acc_o[i][j] *= al;
        }
        #pragma unroll 4
        for (int c = 0; c < BKT; c++) {
            float4 v0 = *(const float4*)&Vs[c*QSTR + tx*8];
            float4 v1 = *(const float4*)&Vs[c*QSTR + tx*8 + 4];
            #pragma unroll
            for (int i = 0; i < 4; i++) {
                float p = Ps[(ty*4 + i)*PSTR + c];
                acc_o[i][0] += p * v0.x;
                acc_o[i][1] += p * v0.y;
                acc_o[i][2] += p * v0.z;
                acc_o[i][3] += p * v0.w;
                acc_o[i][4] += p * v1.x;
                acc_o[i][5] += p * v1.y;
                acc_o[i][6] += p * v1.z;
                acc_o[i][7] += p * v1.w;
            }
        }
        __syncthreads();
    }

    // Normalize and write to (b, n, h, d) layout
    #pragma unroll
    for (int i = 0; i < 4; i++) {
        float inv_l = 1.f / row_l[ty*4 + i];
        size_t base = ((size_t)(b*SEQ + q0 + ty*4 + i)) * CDIM + h*HD + tx*8;
        float4 w0, w1;
        w0.x = acc_o[i][0]*inv_l; w0.y = acc_o[i][1]*inv_l;
        w0.z = acc_o[i][2]*inv_l; w0.w = acc_o[i][3]*inv_l;
        w1.x = acc_o[i][4]*inv_l; w1.y = acc_o[i][5]*inv_l;
        w1.z = acc_o[i][6]*inv_l; w1.w = acc_o[i][7]*inv_l;
        *(float4*)&o[base]     = w0;
        *(float4*)&o[base + 4] = w1;
    }
}

// ---------------------------------------------------------------------------
extern "C" void kernel_launch(void* const* d_in, const int* in_sizes, int n_in,
                              void* d_out, int out_size)
{
    const float* x   = (const float*)d_in[0];
    const int*   pid = (const int*)d_in[1];
    const float* Wq  = (const float*)d_in[2];
    const float* bq  = (const float*)d_in[3];
    const float* Wk  = (const float*)d_in[4];
    const float* bk  = (const float*)d_in[5];
    const float* Wv  = (const float*)d_in[6];
    const float* bv  = (const float*)d_in[7];
    const float* Wo  = (const float*)d_in[8];
    float* out = (float*)d_out;

    float *q, *k, *v, *attn;
    cudaGetSymbolAddress((void**)&q,    g_q);
    cudaGetSymbolAddress((void**)&k,    g_k);
    cudaGetSymbolAddress((void**)&v,    g_v);
    cudaGetSymbolAddress((void**)&attn, g_attn);

    const int M = BATCH * SEQ;   // 4096
    dim3 blk(256);

    // Projections
    sgemm_bias<<<dim3(CDIM/BN, M/BM), blk>>>(x, Wq, bq, q, M, CDIM, CDIM);
    sgemm_bias<<<dim3(KVC/BN,  M/BM), blk>>>(x, Wk, bk, k, M, KVC,  CDIM);
    sgemm_bias<<<dim3(KVC/BN,  M/BM), blk>>>(x, Wv, bv, v, M, KVC,  CDIM);

    // RoPE (q and k)
    int qpairs = BATCH*SEQ*CDIM/2;
    rope_kernel<<<(qpairs + 255)/256, 256>>>(q, pid, CDIM, qpairs);
    int kpairs = BATCH*SEQ*KVC/2;
    rope_kernel<<<(kpairs + 255)/256, 256>>>(k, pid, KVC, kpairs);

    // Flash attention
    int smem_bytes = (3*BQ*QSTR + BQ*PSTR + 3*BQ) * (int)sizeof(float);  // 119552
    cudaFuncSetAttribute(flash_attn, cudaFuncAttributeMaxDynamicSharedMemorySize,
                         smem_bytes);
    flash_attn<<<dim3(SEQ/BQ, BATCH*NH), blk, smem_bytes>>>(q, k, v, attn);

    // Output projection straight into d_out
    sgemm_bias<<<dim3(CDIM/BN, M/BM), blk>>>(attn, Wo, nullptr, out, M, CDIM, CDIM);
}

// round 3
// speedup vs baseline: 1.4040x; 1.4040x over previous
#include <cuda_runtime.h>
#include <cuda_bf16.h>
#include <math.h>
#include <stdint.h>

#define BATCH 2
#define SEQ   2048
#define CDIM  2048
#define NH    16
#define NKV   4
#define HD    128
#define KVC   (NKV*HD)   // 512
#define GRP   (NH/NKV)   // 4

// ---------------- scratch (__device__ globals; no cudaMalloc allowed) -------
__device__ float g_q[BATCH*SEQ*CDIM];
__device__ float g_k[BATCH*SEQ*KVC];
__device__ float g_v[BATCH*SEQ*KVC];
__device__ float g_attn[BATCH*SEQ*CDIM];

__device__ __nv_bfloat16 g_xhi[BATCH*SEQ*CDIM], g_xlo[BATCH*SEQ*CDIM];
__device__ __nv_bfloat16 g_ahi[BATCH*SEQ*CDIM], g_alo[BATCH*SEQ*CDIM];
// weights transposed to [N, K] layout, split hi/lo
__device__ __nv_bfloat16 g_wq_hi[CDIM*CDIM], g_wq_lo[CDIM*CDIM];
__device__ __nv_bfloat16 g_wk_hi[KVC*CDIM],  g_wk_lo[KVC*CDIM];
__device__ __nv_bfloat16 g_wv_hi[KVC*CDIM],  g_wv_lo[KVC*CDIM];
__device__ __nv_bfloat16 g_wo_hi[CDIM*CDIM], g_wo_lo[CDIM*CDIM];

// ---------------- helpers ---------------------------------------------------
__device__ __forceinline__ uint32_t smem_u32(const void* p) {
    uint32_t a;
    asm("{ .reg .u64 t; cvta.to.shared.u64 t, %1; cvt.u32.u64 %0, t; }"
        : "=r"(a) : "l"(p));
    return a;
}
__device__ __forceinline__ void cp16(uint32_t dst, const void* src) {
    asm volatile("cp.async.cg.shared.global [%0], [%1], 16;"
                 :: "r"(dst), "l"(src));
}
__device__ __forceinline__ void cp_commit() {
    asm volatile("cp.async.commit_group;");
}
template <int N>
__device__ __forceinline__ void cp_wait() {
    asm volatile("cp.async.wait_group %0;" :: "n"(N));
}
__device__ __forceinline__ void ldsm4(uint32_t* r, uint32_t addr) {
    asm volatile("ldmatrix.sync.aligned.m8n8.x4.shared.b16 {%0,%1,%2,%3}, [%4];"
                 : "=r"(r[0]), "=r"(r[1]), "=r"(r[2]), "=r"(r[3]) : "r"(addr));
}
__device__ __forceinline__ void mma_bf16(float* c, const uint32_t* a,
                                         const uint32_t* b) {
    asm volatile(
        "mma.sync.aligned.m16n8k16.row.col.f32.bf16.bf16.f32 "
        "{%0,%1,%2,%3}, {%4,%5,%6,%7}, {%8,%9}, {%0,%1,%2,%3};"
        : "+f"(c[0]), "+f"(c[1]), "+f"(c[2]), "+f"(c[3])
        : "r"(a[0]), "r"(a[1]), "r"(a[2]), "r"(a[3]), "r"(b[0]), "r"(b[1]));
}

// ---------------------------------------------------------------------------
// Conversion kernels
// ---------------------------------------------------------------------------
__global__ void split_fp32(const float* __restrict__ src,
                           __nv_bfloat16* __restrict__ hi,
                           __nv_bfloat16* __restrict__ lo, int n) {
    int i = blockIdx.x * blockDim.x + threadIdx.x;
    if (i >= n) return;
    float x = src[i];
    __nv_bfloat16 h = __float2bfloat16(x);
    hi[i] = h;
    lo[i] = __float2bfloat16(x - __bfloat162float(h));
}

// W [K, Nn] fp32  ->  hi/lo [Nn, K] bf16 (transposed)
__global__ __launch_bounds__(256) void transpose_split(
    const float* __restrict__ W,
    __nv_bfloat16* __restrict__ hi, __nv_bfloat16* __restrict__ lo,
    int K, int Nn) {
    __shared__ float t[32][33];
    int bx = blockIdx.x * 32;   // n offset
    int by = blockIdx.y * 32;   // k offset
    int tx = threadIdx.x & 31;
    int ty = threadIdx.x >> 5;  // 0..7
    #pragma unroll
    for (int i = 0; i < 32; i += 8)
        t[ty + i][tx] = W[(size_t)(by + ty + i) * Nn + bx + tx];
    __syncthreads();
    #pragma unroll
    for (int i = 0; i < 32; i += 8) {
        int r = ty + i;                    // n local
        float x = t[tx][r];                // = W[by+tx][bx+r]
        __nv_bfloat16 h = __float2bfloat16(x);
        size_t o = (size_t)(bx + r) * K + by + tx;
        hi[o] = h;
        lo[o] = __float2bfloat16(x - __bfloat162float(h));
    }
}

// ---------------------------------------------------------------------------
// bf16x3 GEMM via mma.sync:  C[M,N] = (Ahi+Alo)[M,K] @ ((Bhi+Blo)[N,K])^T + bias
// CTA 128x128, BK=32, 8 warps (4 m x 2 n), warp tile 32x64.
// SMEM tiles padded to 80B rows -> conflict-free ldmatrix; cp.async double buf.
// ---------------------------------------------------------------------------
#define GBM 128
#define GBN 128
#define BKC 32
#define ASTRB 80                  // bytes per smem tile row (40 bf16)
#define TILEB (128*ASTRB)         // 10240 bytes per tile
#define STAGEB (4*TILEB)          // 40960 bytes per stage
#define GSMEM (2*STAGEB)          // 81920

__global__ __launch_bounds__(256) void gemm_bf16x3(
    const __nv_bfloat16* __restrict__ Ahi, const __nv_bfloat16* __restrict__ Alo,
    const __nv_bfloat16* __restrict__ Bhi, const __nv_bfloat16* __restrict__ Blo,
    const float* __restrict__ bias, float* __restrict__ C,
    int Nd, int K) {
    extern __shared__ char smem[];
    const uint32_t sb = smem_u32(smem);
    const int tid = threadIdx.x;
    const int wid = tid >> 5;
    const int lane = tid & 31;
    const int m0 = blockIdx.y * GBM;
    const int n0 = blockIdx.x * GBN;

    const int mbase = (wid & 3) * 32;   // warp m offset (0,32,64,96)
    const int nbase = (wid >> 2) * 64;  // warp n offset (0,64)

    // per-thread ldmatrix smem offsets (within a tile)
    const uint32_t aoff = (uint32_t)(mbase + (lane & 15)) * ASTRB + (lane >> 4) * 16;
    const uint32_t boff = (uint32_t)(nbase + ((lane >> 4) << 3) + (lane & 7)) * ASTRB
                        + ((lane >> 3) & 1) * 16;

    // global load mapping: 2048 16B chunks/stage, 8 per thread
    const __nv_bfloat16* gbase[4] = {Ahi, Alo, Bhi, Blo};
    const int rowoff[4] = {m0, m0, n0, n0};

    float acc[2][8][4];
    #pragma unroll
    for (int mi = 0; mi < 2; mi++)
        #pragma unroll
        for (int j = 0; j < 8; j++)
            #pragma unroll
            for (int e = 0; e < 4; e++) acc[mi][j][e] = 0.f;

    const int nchunks = K / BKC;

    // ---- load stage 0 ----
    {
        const int kk = 0;
        #pragma unroll
        for (int t = 0; t < 8; t++) {
            int c = tid + t * 256;
            int tile = c >> 9;
            int cc = c & 511;
            int row = cc >> 2, c16 = cc & 3;
            uint32_t dst = sb + tile * TILEB + row * ASTRB + c16 * 16;
            const __nv_bfloat16* src =
                gbase[tile] + (size_t)(rowoff[tile] + row) * K + kk + c16 * 8;
            cp16(dst, src);
        }
        cp_commit();
    }

    for (int kc = 0; kc < nchunks; kc++) {
        if (kc + 1 < nchunks) {
            const int kk = (kc + 1) * BKC;
            const uint32_t st = sb + ((kc + 1) & 1) * STAGEB;
            #pragma unroll
            for (int t = 0; t < 8; t++) {
                int c = tid + t * 256;
                int tile = c >> 9;
                int cc = c & 511;
                int row = cc >> 2, c16 = cc & 3;
                uint32_t dst = st + tile * TILEB + row * ASTRB + c16 * 16;
                const __nv_bfloat16* src =
                    gbase[tile] + (size_t)(rowoff[tile] + row) * K + kk + c16 * 8;
                cp16(dst, src);
            }
            cp_commit();
            cp_wait<1>();
        } else {
            cp_wait<0>();
        }
        __syncthreads();

        const uint32_t st = sb + (kc & 1) * STAGEB;
        #pragma unroll
        for (int ks = 0; ks < 2; ks++) {
            uint32_t ah[2][4], al[2][4];
            #pragma unroll
            for (int mi = 0; mi < 2; mi++) {
                ldsm4(ah[mi], st + aoff + mi * (16 * ASTRB) + ks * 32);
                ldsm4(al[mi], st + TILEB + aoff + mi * (16 * ASTRB) + ks * 32);
            }
            #pragma unroll
            for (int np = 0; np < 4; np++) {
                uint32_t bh[4], bl[4];
                ldsm4(bh, st + 2 * TILEB + boff + np * (16 * ASTRB) + ks * 32);
                ldsm4(bl, st + 3 * TILEB + boff + np * (16 * ASTRB) + ks * 32);
                #pragma unroll
                for (int mi = 0; mi < 2; mi++) {
                    mma_bf16(acc[mi][np * 2],     ah[mi], bh);
                    mma_bf16(acc[mi][np * 2],     ah[mi], bl);
                    mma_bf16(acc[mi][np * 2],     al[mi], bh);
                    mma_bf16(acc[mi][np * 2 + 1], ah[mi], bh + 2);
                    mma_bf16(acc[mi][np * 2 + 1], ah[mi], bl + 2);
                    mma_bf16(acc[mi][np * 2 + 1], al[mi], bh + 2);
                }
            }
        }
        __syncthreads();
    }

    // ---- epilogue ----
    const int r0 = lane >> 2;
    const int c0 = (lane & 3) * 2;
    #pragma unroll
    for (int mi = 0; mi < 2; mi++) {
        const int rowa = m0 + mbase + mi * 16 + r0;
        #pragma unroll
        for (int j = 0; j < 8; j++) {
            const int col = n0 + nbase + j * 8 + c0;
            float bx = 0.f, by = 0.f;
            if (bias) { bx = bias[col]; by = bias[col + 1]; }
            float2 v0 = make_float2(acc[mi][j][0] + bx, acc[mi][j][1] + by);
            float2 v1 = make_float2(acc[mi][j][2] + bx, acc[mi][j][3] + by);
            *(float2*)&C[(size_t)rowa * Nd + col] = v0;
            *(float2*)&C[(size_t)(rowa + 8) * Nd + col] = v1;
        }
    }
}

// ---------------------------------------------------------------------------
// Interleaved RoPE
// ---------------------------------------------------------------------------
__global__ void rope_kernel(float* __restrict__ buf, const int* __restrict__ pos_ids,
                            int W, int total_pairs) {
    int p = blockIdx.x * blockDim.x + threadIdx.x;
    if (p >= total_pairs) return;
    int halfW = W >> 1;
    int row = p / halfW;
    int j = p - row * halfW;
    int i = j & (HD / 2 - 1);
    int head = j >> 6;
    float pos = (float)pos_ids[row];
    float inv = expf(-(2.0f * (float)i / (float)HD) * 9.210340371976184f);
    float ang = pos * inv;
    float s, c;
    sincosf(ang, &s, &c);
    float* x = buf + (size_t)row * W + head * HD + 2 * i;
    float x0 = x[0], x1 = x[1];
    x[0] = x0 * c - x1 * s;
    x[1] = x1 * c + x0 * s;
}

// ---------------------------------------------------------------------------
// Causal GQA flash attention, fp32 SIMT (known-good from R1)
// ---------------------------------------------------------------------------
#define BQ   64
#define BKT  64
#define QSTR 132
#define PSTR 68

__global__ __launch_bounds__(256) void flash_attn(
    const float* __restrict__ q, const float* __restrict__ k,
    const float* __restrict__ v, float* __restrict__ o) {
    extern __shared__ float sm[];
    float* Qs    = sm;
    float* Ks    = Qs + BQ * QSTR;
    float* Vs    = Ks + BKT * QSTR;
    float* Ps    = Vs + BKT * QSTR;
    float* row_m = Ps + BQ * PSTR;
    float* row_l = row_m + BQ;
    float* row_a = row_l + BQ;

    const int tid = threadIdx.x;
    const int ty = tid >> 4;
    const int tx = tid & 15;
    const int qt = blockIdx.x;
    const int bh = blockIdx.y;
    const int b = bh / NH, h = bh % NH;
    const int kvh = h / GRP;
    const int q0 = qt * BQ;

    for (int f = tid; f < BQ * 32; f += 256) {
        int row = f >> 5, c4 = f & 31;
        *(float4*)&Qs[row * QSTR + c4 * 4] =
            *(const float4*)&q[((size_t)(b * SEQ + q0 + row)) * CDIM + h * HD + c4 * 4];
    }
    if (tid < BQ) { row_m[tid] = -1e30f; row_l[tid] = 0.f; }

    float acc_o[4][8];
    #pragma unroll
    for (int i = 0; i < 4; i++)
        #pragma unroll
        for (int j = 0; j < 8; j++) acc_o[i][j] = 0.f;

    __syncthreads();

    const float scale = 0.08838834764831845f;

    for (int kt = 0; kt <= qt; kt++) {
        const int k0 = kt * BKT;
        for (int f = tid; f < BKT * 32; f += 256) {
            int row = f >> 5, c4 = f & 31;
            size_t gofs = ((size_t)(b * SEQ + k0 + row)) * KVC + kvh * HD + c4 * 4;
            *(float4*)&Ks[row * QSTR + c4 * 4] = *(const float4*)&k[gofs];
            *(float4*)&Vs[row * QSTR + c4 * 4] = *(const float4*)&v[gofs];
        }
        __syncthreads();

        float sacc[4][4];
        #pragma unroll
        for (int i = 0; i < 4; i++)
            #pragma unroll
            for (int j = 0; j < 4; j++) sacc[i][j] = 0.f;

        #pragma unroll 4
        for (int d = 0; d < HD; d += 4) {
            float4 qv[4], kv4[4];
            #pragma unroll
            for (int i = 0; i < 4; i++)
                qv[i] = *(const float4*)&Qs[(ty * 4 + i) * QSTR + d];
            #pragma unroll
            for (int j = 0; j < 4; j++)
                kv4[j] = *(const float4*)&Ks[(tx * 4 + j) * QSTR + d];
            #pragma unroll
            for (int i = 0; i < 4; i++)
                #pragma unroll
                for (int j = 0; j < 4; j++)
                    sacc[i][j] += qv[i].x * kv4[j].x + qv[i].y * kv4[j].y
                                + qv[i].z * kv4[j].z + qv[i].w * kv4[j].w;
        }

        #pragma unroll
        for (int i = 0; i < 4; i++) {
            const int r = ty * 4 + i;
            const int rg = q0 + r;
            float p4[4];
            float mx = -1e30f;
            #pragma unroll
            for (int j = 0; j < 4; j++) {
                float sv = sacc[i][j] * scale;
                if (k0 + tx * 4 + j > rg) sv = -1e30f;
                sacc[i][j] = sv;
                mx = fmaxf(mx, sv);
            }
            #pragma unroll
            for (int off = 8; off > 0; off >>= 1)
                mx = fmaxf(mx, __shfl_xor_sync(0xffffffffu, mx, off));

            float m_old = row_m[r];
            float m_new = fmaxf(m_old, mx);
            float sum = 0.f;
            #pragma unroll
            for (int j = 0; j < 4; j++) {
                float pv = __expf(sacc[i][j] - m_new);
                p4[j] = pv;
                sum += pv;
            }
            #pragma unroll
            for (int off = 8; off > 0; off >>= 1)
                sum += __shfl_xor_sync(0xffffffffu, sum, off);

            if (tx == 0) {
                float alpha = __expf(m_old - m_new);
                row_a[r] = alpha;
                row_l[r] = row_l[r] * alpha + sum;
                row_m[r] = m_new;
            }
            #pragma unroll
            for (int j = 0; j < 4; j++)
                Ps[r * PSTR + tx * 4 + j] = p4[j];
        }
        __syncthreads();

        #pragma unroll
        for (int i = 0; i < 4; i++) {
            float al = row_a[ty * 4 + i];
            #pragma unroll
            for (int j = 0; j < 8; j++) acc_o[i][j] *= al;
        }
        #pragma unroll 4
        for (int c = 0; c < BKT; c++) {
            float4 v0 = *(const float4*)&Vs[c * QSTR + tx * 8];
            float4 v1 = *(const float4*)&Vs[c * QSTR + tx * 8 + 4];
            #pragma unroll
            for (int i = 0; i < 4; i++) {
                float p = Ps[(ty * 4 + i) * PSTR + c];
                acc_o[i][0] += p * v0.x;
                acc_o[i][1] += p * v0.y;
                acc_o[i][2] += p * v0.z;
                acc_o[i][3] += p * v0.w;
                acc_o[i][4] += p * v1.x;
                acc_o[i][5] += p * v1.y;
                acc_o[i][6] += p * v1.z;
                acc_o[i][7] += p * v1.w;
            }
        }
        __syncthreads();
    }

    #pragma unroll
    for (int i = 0; i < 4; i++) {
        float inv_l = 1.f / row_l[ty * 4 + i];
        size_t base = ((size_t)(b * SEQ + q0 + ty * 4 + i)) * CDIM + h * HD + tx * 8;
        float4 w0, w1;
        w0.x = acc_o[i][0] * inv_l; w0.y = acc_o[i][1] * inv_l;
        w0.z = acc_o[i][2] * inv_l; w0.w = acc_o[i][3] * inv_l;
        w1.x = acc_o[i][4] * inv_l; w1.y = acc_o[i][5] * inv_l;
        w1.z = acc_o[i][6] * inv_l; w1.w = acc_o[i][7] * inv_l;
        *(float4*)&o[base]     = w0;
        *(float4*)&o[base + 4] = w1;
    }
}

// ---------------------------------------------------------------------------
extern "C" void kernel_launch(void* const* d_in, const int* in_sizes, int n_in,
                              void* d_out, int out_size) {
    const float* x   = (const float*)d_in[0];
    const int*   pid = (const int*)d_in[1];
    const float* Wq  = (const float*)d_in[2];
    const float* bq  = (const float*)d_in[3];
    const float* Wk  = (const float*)d_in[4];
    const float* bk  = (const float*)d_in[5];
    const float* Wv  = (const float*)d_in[6];
    const float* bv  = (const float*)d_in[7];
    const float* Wo  = (const float*)d_in[8];
    float* out = (float*)d_out;

    float *q, *k, *v, *attn;
    cudaGetSymbolAddress((void**)&q,    g_q);
    cudaGetSymbolAddress((void**)&k,    g_k);
    cudaGetSymbolAddress((void**)&v,    g_v);
    cudaGetSymbolAddress((void**)&attn, g_attn);
    __nv_bfloat16 *xhi, *xlo, *ahi, *alo;
    __nv_bfloat16 *wqh, *wql, *wkh, *wkl, *wvh, *wvl, *woh, *wol;
    cudaGetSymbolAddress((void**)&xhi, g_xhi);
    cudaGetSymbolAddress((void**)&xlo, g_xlo);
    cudaGetSymbolAddress((void**)&ahi, g_ahi);
    cudaGetSymbolAddress((void**)&alo, g_alo);
    cudaGetSymbolAddress((void**)&wqh, g_wq_hi);
    cudaGetSymbolAddress((void**)&wql, g_wq_lo);
    cudaGetSymbolAddress((void**)&wkh, g_wk_hi);
    cudaGetSymbolAddress((void**)&wkl, g_wk_lo);
    cudaGetSymbolAddress((void**)&wvh, g_wv_hi);
    cudaGetSymbolAddress((void**)&wvl, g_wv_lo);
    cudaGetSymbolAddress((void**)&woh, g_wo_hi);
    cudaGetSymbolAddress((void**)&wol, g_wo_lo);

    const int M = BATCH * SEQ;   // 4096

    // --- precision-split conversions ---
    int nx = M * CDIM;
    split_fp32<<<(nx + 255) / 256, 256>>>(x, xhi, xlo, nx);
    transpose_split<<<dim3(CDIM / 32, CDIM / 32), 256>>>(Wq, wqh, wql, CDIM, CDIM);
    transpose_split<<<dim3(KVC / 32,  CDIM / 32), 256>>>(Wk, wkh, wkl, CDIM, KVC);
    transpose_split<<<dim3(KVC / 32,  CDIM / 32), 256>>>(Wv, wvh, wvl, CDIM, KVC);
    transpose_split<<<dim3(CDIM / 32, CDIM / 32), 256>>>(Wo, woh, wol, CDIM, CDIM);

    // --- projections on mma.sync bf16x3 ---
    cudaFuncSetAttribute(gemm_bf16x3, cudaFuncAttributeMaxDynamicSharedMemorySize, GSMEM);
    gemm_bf16x3<<<dim3(CDIM / GBN, M / GBM), 256, GSMEM>>>(xhi, xlo, wqh, wql, bq, q, CDIM, CDIM);
    gemm_bf16x3<<<dim3(KVC / GBN,  M / GBM), 256, GSMEM>>>(xhi, xlo, wkh, wkl, bk, k, KVC, CDIM);
    gemm_bf16x3<<<dim3(KVC / GBN,  M / GBM), 256, GSMEM>>>(xhi, xlo, wvh, wvl, bv, v, KVC, CDIM);

    // --- RoPE ---
    int qpairs = M * CDIM / 2;
    rope_kernel<<<(qpairs + 255) / 256, 256>>>(q, pid, CDIM, qpairs);
    int kpairs = M * KVC / 2;
    rope_kernel<<<(kpairs + 255) / 256, 256>>>(k, pid, KVC, kpairs);

    // --- attention (fp32 SIMT) ---
    int smem_bytes = (3 * BQ * QSTR + BQ * PSTR + 3 * BQ) * (int)sizeof(float);
    cudaFuncSetAttribute(flash_attn, cudaFuncAttributeMaxDynamicSharedMemorySize, smem_bytes);
    flash_attn<<<dim3(SEQ / BQ, BATCH * NH), 256, smem_bytes>>>(q, k, v, attn);

    // --- output projection ---
    int na = M * CDIM;
    split_fp32<<<(na + 255) / 256, 256>>>(attn, ahi, alo, na);
    gemm_bf16x3<<<dim3(CDIM / GBN, M / GBM), 256, GSMEM>>>(ahi, alo, woh, wol, nullptr, out, CDIM, CDIM);
}

// round 4
// speedup vs baseline: 3.2631x; 2.3241x over previous
#include <cuda_runtime.h>
#include <cuda_bf16.h>
#include <math.h>
#include <stdint.h>

#define BATCH 2
#define SEQ   2048
#define CDIM  2048
#define NH    16
#define NKV   4
#define HD    128
#define KVC   (NKV*HD)   // 512
#define GRP   (NH/NKV)   // 4

// ---------------- scratch (__device__ globals; no cudaMalloc allowed) -------
__device__ float g_q[BATCH*SEQ*CDIM];
__device__ float g_k[BATCH*SEQ*KVC];
__device__ float g_v[BATCH*SEQ*KVC];
__device__ float g_attn[BATCH*SEQ*CDIM];

__device__ __nv_bfloat16 g_xhi[BATCH*SEQ*CDIM], g_xlo[BATCH*SEQ*CDIM];
__device__ __nv_bfloat16 g_ahi[BATCH*SEQ*CDIM], g_alo[BATCH*SEQ*CDIM];
// attention operands, bf16 hi/lo
__device__ __nv_bfloat16 g_qhi[BATCH*SEQ*CDIM], g_qlo[BATCH*SEQ*CDIM];
__device__ __nv_bfloat16 g_khi[BATCH*SEQ*KVC],  g_klo[BATCH*SEQ*KVC];
__device__ __nv_bfloat16 g_vhi[BATCH*SEQ*KVC],  g_vlo[BATCH*SEQ*KVC];
// weights transposed to [N, K] layout, split hi/lo
__device__ __nv_bfloat16 g_wq_hi[CDIM*CDIM], g_wq_lo[CDIM*CDIM];
__device__ __nv_bfloat16 g_wk_hi[KVC*CDIM],  g_wk_lo[KVC*CDIM];
__device__ __nv_bfloat16 g_wv_hi[KVC*CDIM],  g_wv_lo[KVC*CDIM];
__device__ __nv_bfloat16 g_wo_hi[CDIM*CDIM], g_wo_lo[CDIM*CDIM];

// ---------------- helpers ---------------------------------------------------
__device__ __forceinline__ uint32_t smem_u32(const void* p) {
    uint32_t a;
    asm("{ .reg .u64 t; cvta.to.shared.u64 t, %1; cvt.u32.u64 %0, t; }"
        : "=r"(a) : "l"(p));
    return a;
}
__device__ __forceinline__ void cp16(uint32_t dst, const void* src) {
    asm volatile("cp.async.cg.shared.global [%0], [%1], 16;"
                 :: "r"(dst), "l"(src));
}
__device__ __forceinline__ void cp_commit() {
    asm volatile("cp.async.commit_group;");
}
template <int N>
__device__ __forceinline__ void cp_wait() {
    asm volatile("cp.async.wait_group %0;" :: "n"(N));
}
__device__ __forceinline__ void ldsm4(uint32_t* r, uint32_t addr) {
    asm volatile("ldmatrix.sync.aligned.m8n8.x4.shared.b16 {%0,%1,%2,%3}, [%4];"
                 : "=r"(r[0]), "=r"(r[1]), "=r"(r[2]), "=r"(r[3]) : "r"(addr));
}
__device__ __forceinline__ void ldsm4t(uint32_t* r, uint32_t addr) {
    asm volatile("ldmatrix.sync.aligned.m8n8.x4.trans.shared.b16 {%0,%1,%2,%3}, [%4];"
                 : "=r"(r[0]), "=r"(r[1]), "=r"(r[2]), "=r"(r[3]) : "r"(addr));
}
__device__ __forceinline__ void mma_bf16(float* c, const uint32_t* a,
                                         const uint32_t* b) {
    asm volatile(
        "mma.sync.aligned.m16n8k16.row.col.f32.bf16.bf16.f32 "
        "{%0,%1,%2,%3}, {%4,%5,%6,%7}, {%8,%9}, {%0,%1,%2,%3};"
        : "+f"(c[0]), "+f"(c[1]), "+f"(c[2]), "+f"(c[3])
        : "r"(a[0]), "r"(a[1]), "r"(a[2]), "r"(a[3]), "r"(b[0]), "r"(b[1]));
}
__device__ __forceinline__ uint32_t packbf(float lo, float hi) {
    uint32_t r;
    asm("cvt.rn.bf16x2.f32 %0, %1, %2;" : "=r"(r) : "f"(hi), "f"(lo));
    return r;
}

// ---------------------------------------------------------------------------
// Conversion kernels
// ---------------------------------------------------------------------------
__global__ void split_fp32(const float* __restrict__ src,
                           __nv_bfloat16* __restrict__ hi,
                           __nv_bfloat16* __restrict__ lo, int n) {
    int i = blockIdx.x * blockDim.x + threadIdx.x;
    if (i >= n) return;
    float x = src[i];
    __nv_bfloat16 h = __float2bfloat16(x);
    hi[i] = h;
    lo[i] = __float2bfloat16(x - __bfloat162float(h));
}

// RoPE + scale + hi/lo split in one pass.
__global__ void rope_split(const float* __restrict__ in,
                           __nv_bfloat16* __restrict__ hi,
                           __nv_bfloat16* __restrict__ lo,
                           const int* __restrict__ pos_ids,
                           int W, float scale, int total_pairs) {
    int p = blockIdx.x * blockDim.x + threadIdx.x;
    if (p >= total_pairs) return;
    int halfW = W >> 1;
    int row = p / halfW;
    int j = p - row * halfW;
    int i = j & (HD / 2 - 1);
    int head = j >> 6;
    float pos = (float)pos_ids[row];
    float inv = expf(-(2.0f * (float)i / (float)HD) * 9.210340371976184f);
    float ang = pos * inv;
    float s, c;
    sincosf(ang, &s, &c);
    size_t o = (size_t)row * W + head * HD + 2 * i;
    float x0 = in[o], x1 = in[o + 1];
    float y0 = (x0 * c - x1 * s) * scale;
    float y1 = (x1 * c + x0 * s) * scale;
    __nv_bfloat16 h0 = __float2bfloat16(y0);
    __nv_bfloat16 h1 = __float2bfloat16(y1);
    hi[o] = h0;     hi[o + 1] = h1;
    lo[o] = __float2bfloat16(y0 - __bfloat162float(h0));
    lo[o + 1] = __float2bfloat16(y1 - __bfloat162float(h1));
}

// W [K, Nn] fp32  ->  hi/lo [Nn, K] bf16 (transposed)
__global__ __launch_bounds__(256) void transpose_split(
    const float* __restrict__ W,
    __nv_bfloat16* __restrict__ hi, __nv_bfloat16* __restrict__ lo,
    int K, int Nn) {
    __shared__ float t[32][33];
    int bx = blockIdx.x * 32;
    int by = blockIdx.y * 32;
    int tx = threadIdx.x & 31;
    int ty = threadIdx.x >> 5;
    #pragma unroll
    for (int i = 0; i < 32; i += 8)
        t[ty + i][tx] = W[(size_t)(by + ty + i) * Nn + bx + tx];
    __syncthreads();
    #pragma unroll
    for (int i = 0; i < 32; i += 8) {
        int r = ty + i;
        float x = t[tx][r];
        __nv_bfloat16 h = __float2bfloat16(x);
        size_t o = (size_t)(bx + r) * K + by + tx;
        hi[o] = h;
        lo[o] = __float2bfloat16(x - __bfloat162float(h));
    }
}

// ---------------------------------------------------------------------------
// bf16x3 GEMM via mma.sync (unchanged from R3, passing)
// ---------------------------------------------------------------------------
#define GBM 128
#define GBN 128
#define BKC 32
#define ASTRB 80
#define TILEB (128*ASTRB)
#define STAGEB (4*TILEB)
#define GSMEM (2*STAGEB)

__global__ __launch_bounds__(256) void gemm_bf16x3(
    const __nv_bfloat16* __restrict__ Ahi, const __nv_bfloat16* __restrict__ Alo,
    const __nv_bfloat16* __restrict__ Bhi, const __nv_bfloat16* __restrict__ Blo,
    const float* __restrict__ bias, float* __restrict__ C,
    int Nd, int K) {
    extern __shared__ char smem[];
    const uint32_t sb = smem_u32(smem);
    const int tid = threadIdx.x;
    const int wid = tid >> 5;
    const int lane = tid & 31;
    const int m0 = blockIdx.y * GBM;
    const int n0 = blockIdx.x * GBN;

    const int mbase = (wid & 3) * 32;
    const int nbase = (wid >> 2) * 64;

    const uint32_t aoff = (uint32_t)(mbase + (lane & 15)) * ASTRB + (lane >> 4) * 16;
    const uint32_t boff = (uint32_t)(nbase + ((lane >> 4) << 3) + (lane & 7)) * ASTRB
                        + ((lane >> 3) & 1) * 16;

    const __nv_bfloat16* gbase[4] = {Ahi, Alo, Bhi, Blo};
    const int rowoff[4] = {m0, m0, n0, n0};

    float acc[2][8][4];
    #pragma unroll
    for (int mi = 0; mi < 2; mi++)
        #pragma unroll
        for (int j = 0; j < 8; j++)
            #pragma unroll
            for (int e = 0; e < 4; e++) acc[mi][j][e] = 0.f;

    const int nchunks = K / BKC;

    {
        #pragma unroll
        for (int t = 0; t < 8; t++) {
            int c = tid + t * 256;
            int tile = c >> 9;
            int cc = c & 511;
            int row = cc >> 2, c16 = cc & 3;
            uint32_t dst = sb + tile * TILEB + row * ASTRB + c16 * 16;
            const __nv_bfloat16* src =
                gbase[tile] + (size_t)(rowoff[tile] + row) * K + c16 * 8;
            cp16(dst, src);
        }
        cp_commit();
    }

    for (int kc = 0; kc < nchunks; kc++) {
        if (kc + 1 < nchunks) {
            const int kk = (kc + 1) * BKC;
            const uint32_t st = sb + ((kc + 1) & 1) * STAGEB;
            #pragma unroll
            for (int t = 0; t < 8; t++) {
                int c = tid + t * 256;
                int tile = c >> 9;
                int cc = c & 511;
                int row = cc >> 2, c16 = cc & 3;
                uint32_t dst = st + tile * TILEB + row * ASTRB + c16 * 16;
                const __nv_bfloat16* src =
                    gbase[tile] + (size_t)(rowoff[tile] + row) * K + kk + c16 * 8;
                cp16(dst, src);
            }
            cp_commit();
            cp_wait<1>();
        } else {
            cp_wait<0>();
        }
        __syncthreads();

        const uint32_t st = sb + (kc & 1) * STAGEB;
        #pragma unroll
        for (int ks = 0; ks < 2; ks++) {
            uint32_t ah[2][4], al[2][4];
            #pragma unroll
            for (int mi = 0; mi < 2; mi++) {
                ldsm4(ah[mi], st + aoff + mi * (16 * ASTRB) + ks * 32);
                ldsm4(al[mi], st + TILEB + aoff + mi * (16 * ASTRB) + ks * 32);
            }
            #pragma unroll
            for (int np = 0; np < 4; np++) {
                uint32_t bh[4], bl[4];
                ldsm4(bh, st + 2 * TILEB + boff + np * (16 * ASTRB) + ks * 32);
                ldsm4(bl, st + 3 * TILEB + boff + np * (16 * ASTRB) + ks * 32);
                #pragma unroll
                for (int mi = 0; mi < 2; mi++) {
                    mma_bf16(acc[mi][np * 2],     ah[mi], bh);
                    mma_bf16(acc[mi][np * 2],     ah[mi], bl);
                    mma_bf16(acc[mi][np * 2],     al[mi], bh);
                    mma_bf16(acc[mi][np * 2 + 1], ah[mi], bh + 2);
                    mma_bf16(acc[mi][np * 2 + 1], ah[mi], bl + 2);
                    mma_bf16(acc[mi][np * 2 + 1], al[mi], bh + 2);
                }
            }
        }
        __syncthreads();
    }

    const int r0 = lane >> 2;
    const int c0 = (lane & 3) * 2;
    #pragma unroll
    for (int mi = 0; mi < 2; mi++) {
        const int rowa = m0 + mbase + mi * 16 + r0;
        #pragma unroll
        for (int j = 0; j < 8; j++) {
            const int col = n0 + nbase + j * 8 + c0;
            float bx = 0.f, by = 0.f;
            if (bias) { bx = bias[col]; by = bias[col + 1]; }
            float2 v0 = make_float2(acc[mi][j][0] + bx, acc[mi][j][1] + by);
            float2 v1 = make_float2(acc[mi][j][2] + bx, acc[mi][j][3] + by);
            *(float2*)&C[(size_t)rowa * Nd + col] = v0;
            *(float2*)&C[(size_t)(rowa + 8) * Nd + col] = v1;
        }
    }
}

// ---------------------------------------------------------------------------
// Tensor-core causal GQA flash attention (bf16x3 QK^T and PV, fp32 softmax).
// CTA: 64 q rows, 4 warps (16 rows each). KV tiles of 64.
// ---------------------------------------------------------------------------
#define FSTR 272                    // smem row stride bytes (128 bf16 + pad)
#define FTILE (64*FSTR)             // 17408 bytes
#define SM_QHI 0
#define SM_QLO (1*FTILE)
#define SM_KHI (2*FTILE)
#define SM_KLO (3*FTILE)
#define SM_VHI (4*FTILE)
#define SM_VLO (5*FTILE)
#define FSMEM  (6*FTILE)            // 104448

__global__ __launch_bounds__(128) void flash_attn_mma(
    const __nv_bfloat16* __restrict__ qhi, const __nv_bfloat16* __restrict__ qlo,
    const __nv_bfloat16* __restrict__ khi, const __nv_bfloat16* __restrict__ klo,
    const __nv_bfloat16* __restrict__ vhi, const __nv_bfloat16* __restrict__ vlo,
    float* __restrict__ o) {
    extern __shared__ char smem[];
    const uint32_t sb = smem_u32(smem);
    const int tid = threadIdx.x;
    const int warp = tid >> 5;
    const int lane = tid & 31;
    const int qt = blockIdx.x;
    const int bh = blockIdx.y;
    const int b = bh / NH, h = bh % NH;
    const int kvh = h / GRP;
    const int q0 = qt * 64;

    // ---- load Q tile (64 x 128 bf16, hi+lo) ----
    {
        const __nv_bfloat16* qh = qhi + (size_t)(b * SEQ + q0) * CDIM + h * HD;
        const __nv_bfloat16* ql = qlo + (size_t)(b * SEQ + q0) * CDIM + h * HD;
        #pragma unroll
        for (int t = 0; t < 8; t++) {
            int c = tid + t * 128;
            int row = c >> 4, ch = c & 15;
            uint32_t dof = row * FSTR + ch * 16;
            size_t gof = (size_t)row * CDIM + ch * 8;
            cp16(sb + SM_QHI + dof, qh + gof);
            cp16(sb + SM_QLO + dof, ql + gof);
        }
        cp_commit();
    }

    // fragment addresses
    const uint32_t aoff = (uint32_t)(warp * 16 + (lane & 15)) * FSTR + (lane >> 4) * 16;
    const uint32_t boff = (uint32_t)(((lane >> 4) << 3) + (lane & 7)) * FSTR
                        + ((lane >> 3) & 1) * 16;
    const uint32_t voff = (uint32_t)((((lane >> 3) & 1) << 3) + (lane & 7)) * FSTR
                        + (lane >> 4) * 16;

    float oacc[16][4];
    #pragma unroll
    for (int t = 0; t < 16; t++)
        #pragma unroll
        for (int e = 0; e < 4; e++) oacc[t][e] = 0.f;
    float m0v = -1e30f, m1v = -1e30f, l0 = 0.f, l1 = 0.f;

    const __nv_bfloat16* kbh = khi + (size_t)(b * SEQ) * KVC + kvh * HD;
    const __nv_bfloat16* kbl = klo + (size_t)(b * SEQ) * KVC + kvh * HD;
    const __nv_bfloat16* vbh = vhi + (size_t)(b * SEQ) * KVC + kvh * HD;
    const __nv_bfloat16* vbl = vlo + (size_t)(b * SEQ) * KVC + kvh * HD;

    for (int kt = 0; kt <= qt; kt++) {
        const int k0 = kt * 64;
        // ---- load K,V tiles (hi+lo) ----
        #pragma unroll
        for (int t = 0; t < 8; t++) {
            int c = tid + t * 128;
            int row = c >> 4, ch = c & 15;
            uint32_t dof = row * FSTR + ch * 16;
            size_t gof = (size_t)(k0 + row) * KVC + ch * 8;
            cp16(sb + SM_KHI + dof, kbh + gof);
            cp16(sb + SM_KLO + dof, kbl + gof);
            cp16(sb + SM_VHI + dof, vbh + gof);
            cp16(sb + SM_VLO + dof, vbl + gof);
        }
        cp_commit();
        cp_wait<0>();
        __syncthreads();

        // ---- S = Q K^T (64x64 per CTA; 16x64 per warp) ----
        float s[8][4];
        #pragma unroll
        for (int nt = 0; nt < 8; nt++)
            #pragma unroll
            for (int e = 0; e < 4; e++) s[nt][e] = 0.f;

        #pragma unroll
        for (int ks = 0; ks < 8; ks++) {
            uint32_t ah[4], al[4];
            ldsm4(ah, sb + SM_QHI + aoff + ks * 32);
            ldsm4(al, sb + SM_QLO + aoff + ks * 32);
            #pragma unroll
            for (int np = 0; np < 4; np++) {
                uint32_t bh[4], bl[4];
                ldsm4(bh, sb + SM_KHI + boff + np * (16 * FSTR) + ks * 32);
                ldsm4(bl, sb + SM_KLO + boff + np * (16 * FSTR) + ks * 32);
                mma_bf16(s[np * 2],     ah, bh);
                mma_bf16(s[np * 2],     ah, bl);
                mma_bf16(s[np * 2],     al, bh);
                mma_bf16(s[np * 2 + 1], ah, bh + 2);
                mma_bf16(s[np * 2 + 1], ah, bl + 2);
                mma_bf16(s[np * 2 + 1], al, bh + 2);
            }
        }

        // ---- causal mask (diagonal tile only) ----
        const int rg0 = q0 + warp * 16 + (lane >> 2);
        if (kt == qt) {
            #pragma unroll
            for (int nt = 0; nt < 8; nt++) {
                int colb = k0 + nt * 8 + 2 * (lane & 3);
                #pragma unroll
                for (int e = 0; e < 4; e++) {
                    int col = colb + (e & 1);
                    int row = rg0 + ((e >> 1) ? 8 : 0);
                    if (col > row) s[nt][e] = -1e30f;
                }
            }
        }

        // ---- online softmax (rows r0 and r0+8) ----
        float mx0 = -1e30f, mx1 = -1e30f;
        #pragma unroll
        for (int nt = 0; nt < 8; nt++) {
            mx0 = fmaxf(mx0, fmaxf(s[nt][0], s[nt][1]));
            mx1 = fmaxf(mx1, fmaxf(s[nt][2], s[nt][3]));
        }
        mx0 = fmaxf(mx0, __shfl_xor_sync(0xffffffffu, mx0, 1));
        mx0 = fmaxf(mx0, __shfl_xor_sync(0xffffffffu, mx0, 2));
        mx1 = fmaxf(mx1, __shfl_xor_sync(0xffffffffu, mx1, 1));
        mx1 = fmaxf(mx1, __shfl_xor_sync(0xffffffffu, mx1, 2));

        float mn0 = fmaxf(m0v, mx0);
        float mn1 = fmaxf(m1v, mx1);
        float al0 = __expf(m0v - mn0);
        float al1 = __expf(m1v - mn1);
        m0v = mn0; m1v = mn1;

        float sum0 = 0.f, sum1 = 0.f;
        #pragma unroll
        for (int nt = 0; nt < 8; nt++) {
            float p0 = __expf(s[nt][0] - mn0);
            float p1 = __expf(s[nt][1] - mn0);
            float p2 = __expf(s[nt][2] - mn1);
            float p3 = __expf(s[nt][3] - mn1);
            s[nt][0] = p0; s[nt][1] = p1; s[nt][2] = p2; s[nt][3] = p3;
            sum0 += p0 + p1;
            sum1 += p2 + p3;
        }
        sum0 += __shfl_xor_sync(0xffffffffu, sum0, 1);
        sum0 += __shfl_xor_sync(0xffffffffu, sum0, 2);
        sum1 += __shfl_xor_sync(0xffffffffu, sum1, 1);
        sum1 += __shfl_xor_sync(0xffffffffu, sum1, 2);
        l0 = l0 * al0 + sum0;
        l1 = l1 * al1 + sum1;

        #pragma unroll
        for (int t = 0; t < 16; t++) {
            oacc[t][0] *= al0; oacc[t][1] *= al0;
            oacc[t][2] *= al1; oacc[t][3] *= al1;
        }

        // ---- O += P V  (P split hi/lo in registers) ----
        #pragma unroll
        for (int kc = 0; kc < 4; kc++) {
            // build A fragments for k-chunk kc from S tiles 2kc, 2kc+1
            uint32_t pah[4], pal[4];
            #pragma unroll
            for (int half = 0; half < 2; half++) {
                const int nt = 2 * kc + half;
                float p0 = s[nt][0], p1 = s[nt][1], p2 = s[nt][2], p3 = s[nt][3];
                __nv_bfloat16 h0 = __float2bfloat16(p0);
                __nv_bfloat16 h1 = __float2bfloat16(p1);
                __nv_bfloat16 h2 = __float2bfloat16(p2);
                __nv_bfloat16 h3 = __float2bfloat16(p3);
                pah[half * 2 + 0] = packbf(__bfloat162float(h0), __bfloat162float(h1));
                pah[half * 2 + 1] = packbf(__bfloat162float(h2), __bfloat162float(h3));
                pal[half * 2 + 0] = packbf(p0 - __bfloat162float(h0), p1 - __bfloat162float(h1));
                pal[half * 2 + 1] = packbf(p2 - __bfloat162float(h2), p3 - __bfloat162float(h3));
            }
            // pah order must be {a0,a1,a2,a3} = {(r0,k0-7),(r0+8,k0-7),(r0,k8-15),(r0+8,k8-15)}
            // half 0 -> a0,a1 ; half 1 -> a2,a3 : matches layout above.
            #pragma unroll
            for (int dc = 0; dc < 8; dc++) {
                uint32_t vh[4], vl[4];
                ldsm4t(vh, sb + SM_VHI + voff + kc * (16 * FSTR) + dc * 32);
                ldsm4t(vl, sb + SM_VLO + voff + kc * (16 * FSTR) + dc * 32);
                mma_bf16(oacc[dc * 2],     pah, vh);
                mma_bf16(oacc[dc * 2],     pah, vl);
                mma_bf16(oacc[dc * 2],     pal, vh);
                mma_bf16(oacc[dc * 2 + 1], pah, vh + 2);
                mma_bf16(oacc[dc * 2 + 1], pah, vl + 2);
                mma_bf16(oacc[dc * 2 + 1], pal, vh + 2);
            }
        }
        __syncthreads();   // protect K/V smem before next tile's loads
    }

    // ---- normalize and write (b, n, h, d) fp32 ----
    const float il0 = 1.f / l0;
    const float il1 = 1.f / l1;
    const int rowg = b * SEQ + q0 + warp * 16 + (lane >> 2);
    const int colg = h * HD + (lane & 3) * 2;
    #pragma unroll
    for (int nt = 0; nt < 16; nt++) {
        float2 w0 = make_float2(oacc[nt][0] * il0, oacc[nt][1] * il0);
        float2 w1 = make_float2(oacc[nt][2] * il1, oacc[nt][3] * il1);
        *(float2*)&o[(size_t)rowg * CDIM + colg + nt * 8] = w0;
        *(float2*)&o[(size_t)(rowg + 8) * CDIM + colg + nt * 8] = w1;
    }
}

// ---------------------------------------------------------------------------
extern "C" void kernel_launch(void* const* d_in, const int* in_sizes, int n_in,
                              void* d_out, int out_size) {
    const float* x   = (const float*)d_in[0];
    const int*   pid = (const int*)d_in[1];
    const float* Wq  = (const float*)d_in[2];
    const float* bq  = (const float*)d_in[3];
    const float* Wk  = (const float*)d_in[4];
    const float* bk  = (const float*)d_in[5];
    const float* Wv  = (const float*)d_in[6];
    const float* bv  = (const float*)d_in[7];
    const float* Wo  = (const float*)d_in[8];
    float* out = (float*)d_out;

    float *q, *k, *v, *attn;
    cudaGetSymbolAddress((void**)&q,    g_q);
    cudaGetSymbolAddress((void**)&k,    g_k);
    cudaGetSymbolAddress((void**)&v,    g_v);
    cudaGetSymbolAddress((void**)&attn, g_attn);
    __nv_bfloat16 *xhi, *xlo, *ahi, *alo;
    __nv_bfloat16 *qh_, *ql_, *kh_, *kl_, *vh_, *vl_;
    __nv_bfloat16 *wqh, *wql, *wkh, *wkl, *wvh, *wvl, *woh, *wol;
    cudaGetSymbolAddress((void**)&xhi, g_xhi);
    cudaGetSymbolAddress((void**)&xlo, g_xlo);
    cudaGetSymbolAddress((void**)&ahi, g_ahi);
    cudaGetSymbolAddress((void**)&alo, g_alo);
    cudaGetSymbolAddress((void**)&qh_, g_qhi);
    cudaGetSymbolAddress((void**)&ql_, g_qlo);
    cudaGetSymbolAddress((void**)&kh_, g_khi);
    cudaGetSymbolAddress((void**)&kl_, g_klo);
    cudaGetSymbolAddress((void**)&vh_, g_vhi);
    cudaGetSymbolAddress((void**)&vl_, g_vlo);
    cudaGetSymbolAddress((void**)&wqh, g_wq_hi);
    cudaGetSymbolAddress((void**)&wql, g_wq_lo);
    cudaGetSymbolAddress((void**)&wkh, g_wk_hi);
    cudaGetSymbolAddress((void**)&wkl, g_wk_lo);
    cudaGetSymbolAddress((void**)&wvh, g_wv_hi);
    cudaGetSymbolAddress((void**)&wvl, g_wv_lo);
    cudaGetSymbolAddress((void**)&woh, g_wo_hi);
    cudaGetSymbolAddress((void**)&wol, g_wo_lo);

    const int M = BATCH * SEQ;   // 4096

    // --- precision-split conversions ---
    int nx = M * CDIM;
    split_fp32<<<(nx + 255) / 256, 256>>>(x, xhi, xlo, nx);
    transpose_split<<<dim3(CDIM / 32, CDIM / 32), 256>>>(Wq, wqh, wql, CDIM, CDIM);
    transpose_split<<<dim3(KVC / 32,  CDIM / 32), 256>>>(Wk, wkh, wkl, CDIM, KVC);
    transpose_split<<<dim3(KVC / 32,  CDIM / 32), 256>>>(Wv, wvh, wvl, CDIM, KVC);
    transpose_split<<<dim3(CDIM / 32, CDIM / 32), 256>>>(Wo, woh, wol, CDIM, CDIM);

    // --- projections (mma.sync bf16x3) ---
    cudaFuncSetAttribute(gemm_bf16x3, cudaFuncAttributeMaxDynamicSharedMemorySize, GSMEM);
    gemm_bf16x3<<<dim3(CDIM / GBN, M / GBM), 256, GSMEM>>>(xhi, xlo, wqh, wql, bq, q, CDIM, CDIM);
    gemm_bf16x3<<<dim3(KVC / GBN,  M / GBM), 256, GSMEM>>>(xhi, xlo, wkh, wkl, bk, k, KVC, CDIM);
    gemm_bf16x3<<<dim3(KVC / GBN,  M / GBM), 256, GSMEM>>>(xhi, xlo, wvh, wvl, bv, v, KVC, CDIM);

    // --- RoPE + split to bf16 hi/lo (q scaled by 1/sqrt(D)) ---
    const float qscale = 0.08838834764831845f;
    int qpairs = M * CDIM / 2;
    rope_split<<<(qpairs + 255) / 256, 256>>>(q, qh_, ql_, pid, CDIM, qscale, qpairs);
    int kpairs = M * KVC / 2;
    rope_split<<<(kpairs + 255) / 256, 256>>>(k, kh_, kl_, pid, KVC, 1.0f, kpairs);
    int nv = M * KVC;
    split_fp32<<<(nv + 255) / 256, 256>>>(v, vh_, vl_, nv);

    // --- tensor-core flash attention ---
    cudaFuncSetAttribute(flash_attn_mma, cudaFuncAttributeMaxDynamicSharedMemorySize, FSMEM);
    flash_attn_mma<<<dim3(SEQ / 64, BATCH * NH), 128, FSMEM>>>(
        qh_, ql_, kh_, kl_, vh_, vl_, attn);

    // --- output projection ---
    int na = M * CDIM;
    split_fp32<<<(na + 255) / 256, 256>>>(attn, ahi, alo, na);
    gemm_bf16x3<<<dim3(CDIM / GBN, M / GBM), 256, GSMEM>>>(ahi, alo, woh, wol, nullptr, out, CDIM, CDIM);
}

// round 5
// speedup vs baseline: 4.9784x; 1.5257x over previous
#include <cuda_runtime.h>
#include <cuda_fp16.h>
#include <math.h>
#include <stdint.h>

#define BATCH 2
#define SEQ   2048
#define CDIM  2048
#define NH    16
#define NKV   4
#define HD    128
#define KVC   (NKV*HD)   // 512
#define GRP   (NH/NKV)   // 4
#define NQKV  (CDIM+2*KVC) // 3072

// ---------------- scratch (__device__ globals) ------------------------------
__device__ __half g_xh[BATCH*SEQ*CDIM], g_xl[BATCH*SEQ*CDIM];
__device__ __half g_wqkv[NQKV*CDIM];          // [3072, 2048] fp16, row = out col
__device__ __half g_wo[CDIM*CDIM];            // [2048, 2048]
__device__ __half g_qh[BATCH*SEQ*CDIM], g_ql[BATCH*SEQ*CDIM];
__device__ __half g_kh[BATCH*SEQ*KVC];
__device__ __half g_vh[BATCH*SEQ*KVC];
__device__ __half g_oh[BATCH*SEQ*CDIM], g_ol[BATCH*SEQ*CDIM];
__device__ float2 g_cs[SEQ*(HD/2)];           // rope cos/sin table

// ---------------- helpers ---------------------------------------------------
__device__ __forceinline__ uint32_t smem_u32(const void* p) {
    uint32_t a;
    asm("{ .reg .u64 t; cvta.to.shared.u64 t, %1; cvt.u32.u64 %0, t; }"
        : "=r"(a) : "l"(p));
    return a;
}
__device__ __forceinline__ void cp16(uint32_t dst, const void* src) {
    asm volatile("cp.async.cg.shared.global [%0], [%1], 16;"
                 :: "r"(dst), "l"(src));
}
__device__ __forceinline__ void cp_commit() {
    asm volatile("cp.async.commit_group;");
}
template <int N>
__device__ __forceinline__ void cp_wait() {
    asm volatile("cp.async.wait_group %0;" :: "n"(N));
}
__device__ __forceinline__ void ldsm4(uint32_t* r, uint32_t addr) {
    asm volatile("ldmatrix.sync.aligned.m8n8.x4.shared.b16 {%0,%1,%2,%3}, [%4];"
                 : "=r"(r[0]), "=r"(r[1]), "=r"(r[2]), "=r"(r[3]) : "r"(addr));
}
__device__ __forceinline__ void ldsm4t(uint32_t* r, uint32_t addr) {
    asm volatile("ldmatrix.sync.aligned.m8n8.x4.trans.shared.b16 {%0,%1,%2,%3}, [%4];"
                 : "=r"(r[0]), "=r"(r[1]), "=r"(r[2]), "=r"(r[3]) : "r"(addr));
}
__device__ __forceinline__ void mma_f16(float* c, const uint32_t* a,
                                        const uint32_t* b) {
    asm volatile(
        "mma.sync.aligned.m16n8k16.row.col.f32.f16.f16.f32 "
        "{%0,%1,%2,%3}, {%4,%5,%6,%7}, {%8,%9}, {%0,%1,%2,%3};"
        : "+f"(c[0]), "+f"(c[1]), "+f"(c[2]), "+f"(c[3])
        : "r"(a[0]), "r"(a[1]), "r"(a[2]), "r"(a[3]), "r"(b[0]), "r"(b[1]));
}
__device__ __forceinline__ uint32_t packh(float lo, float hi) {
    uint32_t r;
    asm("cvt.rn.f16x2.f32 %0, %1, %2;" : "=r"(r) : "f"(hi), "f"(lo));
    return r;
}

// ---------------------------------------------------------------------------
// Prep kernels
// ---------------------------------------------------------------------------
__global__ void build_cs(float2* cs) {
    int idx = blockIdx.x * blockDim.x + threadIdx.x;
    if (idx >= SEQ * (HD / 2)) return;
    int p = idx >> 6;
    int i = idx & 63;
    float inv = expf(-(2.0f * (float)i / (float)HD) * 9.210340371976184f);
    float ang = (float)p * inv;
    float s, c;
    sincosf(ang, &s, &c);
    cs[idx] = make_float2(c, s);
}

__global__ void split_x(const float* __restrict__ src,
                        __half* __restrict__ hi, __half* __restrict__ lo, int n) {
    int i = blockIdx.x * blockDim.x + threadIdx.x;
    if (i >= n) return;
    float x = src[i];
    __half h = __float2half_rn(x);
    hi[i] = h;
    lo[i] = __float2half_rn(x - __half2float(h));
}

// W [K, Nn] fp32 -> dst[(rowoff+n)*Kd + k] fp16 (transposed, single-rounded)
__global__ __launch_bounds__(256) void transpose_f16(
    const float* __restrict__ W, __half* __restrict__ dst,
    int K, int Nn, int rowoff) {
    __shared__ float t[32][33];
    int bx = blockIdx.x * 32;   // n
    int by = blockIdx.y * 32;   // k
    int tx = threadIdx.x & 31;
    int ty = threadIdx.x >> 5;
    #pragma unroll
    for (int i = 0; i < 32; i += 8)
        t[ty + i][tx] = W[(size_t)(by + ty + i) * Nn + bx + tx];
    __syncthreads();
    #pragma unroll
    for (int i = 0; i < 32; i += 8) {
        int r = ty + i;
        dst[(size_t)(rowoff + bx + r) * K + by + tx] = __float2half_rn(t[tx][r]);
    }
}

// ---------------------------------------------------------------------------
// fp16 2-term GEMM core:  acc = (Ah+Al)[M,K] @ (B[N,K])^T   (fp32 accum)
// CTA 128x128, BK=32, 8 warps (4m x 2n), warp tile 32x64.
// ---------------------------------------------------------------------------
#define GBM 128
#define GBN 128
#define BKC 32
#define ASTRB 80                   // bytes per smem row (32 fp16 = 64B + 16 pad)
#define TILEB (128*ASTRB)          // 10240
#define STAGEB (3*TILEB)           // 30720 (Ah, Al, B)
#define GSMEM (2*STAGEB)           // 61440

#define GEMM_MAINLOOP(AH_, AL_, B_, KDIM_)                                      \
    const uint32_t aoff = (uint32_t)(mbase + (lane & 15)) * ASTRB + (lane >> 4) * 16; \
    const uint32_t boff = (uint32_t)(nbase + ((lane >> 4) << 3) + (lane & 7)) * ASTRB \
                        + ((lane >> 3) & 1) * 16;                               \
    float acc[2][8][4];                                                         \
    _Pragma("unroll")                                                           \
    for (int mi = 0; mi < 2; mi++)                                              \
        _Pragma("unroll")                                                       \
        for (int j = 0; j < 8; j++)                                             \
            _Pragma("unroll")                                                   \
            for (int e = 0; e < 4; e++) acc[mi][j][e] = 0.f;                    \
    const int nchunks = (KDIM_) / BKC;                                          \
    {                                                                           \
        _Pragma("unroll")                                                       \
        for (int t = 0; t < 6; t++) {                                           \
            int c = tid + t * 256;                                              \
            int tile = c >> 9;                                                  \
            int cc = c & 511;                                                   \
            int row = cc >> 2, c16 = cc & 3;                                    \
            uint32_t dst = sb + tile * TILEB + row * ASTRB + c16 * 16;          \
            const __half* src = (tile == 0 ? (AH_) + (size_t)(m0 + row) * (KDIM_) \
                              : tile == 1 ? (AL_) + (size_t)(m0 + row) * (KDIM_) \
                                          : (B_) + (size_t)(n0 + row) * (KDIM_)) \
                              + c16 * 8;                                        \
            cp16(dst, src);                                                     \
        }                                                                       \
        cp_commit();                                                            \
    }                                                                           \
    for (int kc = 0; kc < nchunks; kc++) {                                      \
        if (kc + 1 < nchunks) {                                                 \
            const int kk = (kc + 1) * BKC;                                      \
            const uint32_t st = sb + ((kc + 1) & 1) * STAGEB;                   \
            _Pragma("unroll")                                                   \
            for (int t = 0; t < 6; t++) {                                       \
                int c = tid + t * 256;                                          \
                int tile = c >> 9;                                              \
                int cc = c & 511;                                               \
                int row = cc >> 2, c16 = cc & 3;                                \
                uint32_t dst = st + tile * TILEB + row * ASTRB + c16 * 16;      \
                const __half* src = (tile == 0 ? (AH_) + (size_t)(m0 + row) * (KDIM_) \
                                  : tile == 1 ? (AL_) + (size_t)(m0 + row) * (KDIM_) \
                                              : (B_) + (size_t)(n0 + row) * (KDIM_)) \
                                  + kk + c16 * 8;                               \
                cp16(dst, src);                                                 \
            }                                                                   \
            cp_commit();                                                        \
            cp_wait<1>();                                                       \
        } else {                                                                \
            cp_wait<0>();                                                       \
        }                                                                       \
        __syncthreads();                                                        \
        const uint32_t st = sb + (kc & 1) * STAGEB;                             \
        _Pragma("unroll")                                                       \
        for (int ks = 0; ks < 2; ks++) {                                        \
            uint32_t ah[2][4], al[2][4];                                        \
            _Pragma("unroll")                                                   \
            for (int mi = 0; mi < 2; mi++) {                                    \
                ldsm4(ah[mi], st + aoff + mi * (16 * ASTRB) + ks * 32);         \
                ldsm4(al[mi], st + TILEB + aoff + mi * (16 * ASTRB) + ks * 32); \
            }                                                                   \
            _Pragma("unroll")                                                   \
            for (int np = 0; np < 4; np++) {                                    \
                uint32_t bfr[4];                                                \
                ldsm4(bfr, st + 2 * TILEB + boff + np * (16 * ASTRB) + ks * 32);\
                _Pragma("unroll")                                               \
                for (int mi = 0; mi < 2; mi++) {                                \
                    mma_f16(acc[mi][np * 2],     ah[mi], bfr);                  \
                    mma_f16(acc[mi][np * 2],     al[mi], bfr);                  \
                    mma_f16(acc[mi][np * 2 + 1], ah[mi], bfr + 2);              \
                    mma_f16(acc[mi][np * 2 + 1], al[mi], bfr + 2);              \
                }                                                               \
            }                                                                   \
        }                                                                       \
        __syncthreads();                                                        \
    }

// QKV projection with fused bias + RoPE + fp16 split epilogue
__global__ __launch_bounds__(256) void gemm_qkv(
    const __half* __restrict__ Ah, const __half* __restrict__ Al,
    const __half* __restrict__ Bw,
    const float* __restrict__ bq, const float* __restrict__ bk,
    const float* __restrict__ bv, const int* __restrict__ pid,
    const float2* __restrict__ cs,
    __half* __restrict__ qh, __half* __restrict__ ql,
    __half* __restrict__ kh, __half* __restrict__ vh) {
    extern __shared__ char smem[];
    const uint32_t sb = smem_u32(smem);
    const int tid = threadIdx.x;
    const int wid = tid >> 5;
    const int lane = tid & 31;
    const int m0 = blockIdx.y * GBM;
    const int n0 = blockIdx.x * GBN;
    const int mbase = (wid & 3) * 32;
    const int nbase = (wid >> 2) * 64;

    GEMM_MAINLOOP(Ah, Al, Bw, CDIM)

    // epilogue
    const float qscale = 0.08838834764831845f;
    const int r0 = lane >> 2;
    const int c0q = (lane & 3) * 2;
    const int region = (n0 < CDIM) ? 0 : (n0 < CDIM + KVC ? 1 : 2);
    #pragma unroll
    for (int mi = 0; mi < 2; mi++) {
        const int rowa = m0 + mbase + mi * 16 + r0;
        const int rowb = rowa + 8;
        #pragma unroll
        for (int j = 0; j < 8; j++) {
            const int col = n0 + nbase + j * 8 + c0q;
            float a0 = acc[mi][j][0], a1 = acc[mi][j][1];
            float b0 = acc[mi][j][2], b1 = acc[mi][j][3];
            if (region == 0) {
                a0 += bq[col]; a1 += bq[col + 1];
                b0 += bq[col]; b1 += bq[col + 1];
                int i = (col & (HD - 1)) >> 1;
                float2 c_a = cs[pid[rowa] * 64 + i];
                float2 c_b = cs[pid[rowb] * 64 + i];
                float y0 = (a0 * c_a.x - a1 * c_a.y) * qscale;
                float y1 = (a1 * c_a.x + a0 * c_a.y) * qscale;
                float z0 = (b0 * c_b.x - b1 * c_b.y) * qscale;
                float z1 = (b1 * c_b.x + b0 * c_b.y) * qscale;
                __half h0 = __float2half_rn(y0), h1 = __float2half_rn(y1);
                __half g0 = __float2half_rn(z0), g1 = __float2half_rn(z1);
                *(__half2*)&qh[(size_t)rowa * CDIM + col] = __halves2half2(h0, h1);
                *(__half2*)&qh[(size_t)rowb * CDIM + col] = __halves2half2(g0, g1);
                *(__half2*)&ql[(size_t)rowa * CDIM + col] = __halves2half2(
                    __float2half_rn(y0 - __half2float(h0)),
                    __float2half_rn(y1 - __half2float(h1)));
                *(__half2*)&ql[(size_t)rowb * CDIM + col] = __halves2half2(
                    __float2half_rn(z0 - __half2float(g0)),
                    __float2half_rn(z1 - __half2float(g1)));
            } else if (region == 1) {
                int kc = col - CDIM;
                a0 += bk[kc]; a1 += bk[kc + 1];
                b0 += bk[kc]; b1 += bk[kc + 1];
                int i = (kc & (HD - 1)) >> 1;
                float2 c_a = cs[pid[rowa] * 64 + i];
                float2 c_b = cs[pid[rowb] * 64 + i];
                float y0 = a0 * c_a.x - a1 * c_a.y;
                float y1 = a1 * c_a.x + a0 * c_a.y;
                float z0 = b0 * c_b.x - b1 * c_b.y;
                float z1 = b1 * c_b.x + b0 * c_b.y;
                *(__half2*)&kh[(size_t)rowa * KVC + kc] = __halves2half2(
                    __float2half_rn(y0), __float2half_rn(y1));
                *(__half2*)&kh[(size_t)rowb * KVC + kc] = __halves2half2(
                    __float2half_rn(z0), __float2half_rn(z1));
            } else {
                int vc = col - CDIM - KVC;
                a0 += bv[vc]; a1 += bv[vc + 1];
                b0 += bv[vc]; b1 += bv[vc + 1];
                *(__half2*)&vh[(size_t)rowa * KVC + vc] = __halves2half2(
                    __float2half_rn(a0), __float2half_rn(a1));
                *(__half2*)&vh[(size_t)rowb * KVC + vc] = __halves2half2(
                    __float2half_rn(b0), __float2half_rn(b1));
            }
        }
    }
}

// Output projection: plain fp32 epilogue to d_out
__global__ __launch_bounds__(256) void gemm_out(
    const __half* __restrict__ Ah, const __half* __restrict__ Al,
    const __half* __restrict__ Bw, float* __restrict__ C) {
    extern __shared__ char smem[];
    const uint32_t sb = smem_u32(smem);
    const int tid = threadIdx.x;
    const int wid = tid >> 5;
    const int lane = tid & 31;
    const int m0 = blockIdx.y * GBM;
    const int n0 = blockIdx.x * GBN;
    const int mbase = (wid & 3) * 32;
    const int nbase = (wid >> 2) * 64;

    GEMM_MAINLOOP(Ah, Al, Bw, CDIM)

    const int r0 = lane >> 2;
    const int c0q = (lane & 3) * 2;
    #pragma unroll
    for (int mi = 0; mi < 2; mi++) {
        const int rowa = m0 + mbase + mi * 16 + r0;
        #pragma unroll
        for (int j = 0; j < 8; j++) {
            const int col = n0 + nbase + j * 8 + c0q;
            *(float2*)&C[(size_t)rowa * CDIM + col] =
                make_float2(acc[mi][j][0], acc[mi][j][1]);
            *(float2*)&C[(size_t)(rowa + 8) * CDIM + col] =
                make_float2(acc[mi][j][2], acc[mi][j][3]);
        }
    }
}

// ---------------------------------------------------------------------------
// fp16 2-term causal GQA flash attention.
// Q split (hi/lo), K and V single fp16. CTA: 64 q rows, 4 warps. KV tile 64.
// ---------------------------------------------------------------------------
#define FSTR 272
#define FTILE (64*FSTR)            // 17408
#define SM_QH 0
#define SM_QL (1*FTILE)
#define SM_K  (2*FTILE)
#define SM_V  (3*FTILE)
#define FSMEM (4*FTILE)            // 69632

__global__ __launch_bounds__(128) void flash_attn_f16(
    const __half* __restrict__ qh, const __half* __restrict__ ql,
    const __half* __restrict__ kh, const __half* __restrict__ vh,
    __half* __restrict__ oh, __half* __restrict__ ol) {
    extern __shared__ char smem[];
    const uint32_t sb = smem_u32(smem);
    const int tid = threadIdx.x;
    const int warp = tid >> 5;
    const int lane = tid & 31;
    const int qt = blockIdx.x;
    const int bh_ = blockIdx.y;
    const int b = bh_ / NH, h = bh_ % NH;
    const int kvh = h / GRP;
    const int q0 = qt * 64;

    // load Q tile (hi+lo)
    {
        const __half* qph = qh + (size_t)(b * SEQ + q0) * CDIM + h * HD;
        const __half* qpl = ql + (size_t)(b * SEQ + q0) * CDIM + h * HD;
        #pragma unroll
        for (int t = 0; t < 8; t++) {
            int c = tid + t * 128;
            int row = c >> 4, ch = c & 15;
            uint32_t dof = row * FSTR + ch * 16;
            size_t gof = (size_t)row * CDIM + ch * 8;
            cp16(sb + SM_QH + dof, qph + gof);
            cp16(sb + SM_QL + dof, qpl + gof);
        }
        cp_commit();
    }

    const uint32_t aoff = (uint32_t)(warp * 16 + (lane & 15)) * FSTR + (lane >> 4) * 16;
    const uint32_t boff = (uint32_t)(((lane >> 4) << 3) + (lane & 7)) * FSTR
                        + ((lane >> 3) & 1) * 16;
    const uint32_t voff = (uint32_t)((((lane >> 3) & 1) << 3) + (lane & 7)) * FSTR
                        + (lane >> 4) * 16;

    float oacc[16][4];
    #pragma unroll
    for (int t = 0; t < 16; t++)
        #pragma unroll
        for (int e = 0; e < 4; e++) oacc[t][e] = 0.f;
    float m0v = -1e30f, m1v = -1e30f, l0 = 0.f, l1 = 0.f;

    const __half* kb = kh + (size_t)(b * SEQ) * KVC + kvh * HD;
    const __half* vb = vh + (size_t)(b * SEQ) * KVC + kvh * HD;

    for (int kt = 0; kt <= qt; kt++) {
        const int k0 = kt * 64;
        #pragma unroll
        for (int t = 0; t < 8; t++) {
            int c = tid + t * 128;
            int row = c >> 4, ch = c & 15;
            uint32_t dof = row * FSTR + ch * 16;
            size_t gof = (size_t)(k0 + row) * KVC + ch * 8;
            cp16(sb + SM_K + dof, kb + gof);
            cp16(sb + SM_V + dof, vb + gof);
        }
        cp_commit();
        cp_wait<0>();
        __syncthreads();

        // S = (Qh+Ql) K^T
        float s[8][4];
        #pragma unroll
        for (int nt = 0; nt < 8; nt++)
            #pragma unroll
            for (int e = 0; e < 4; e++) s[nt][e] = 0.f;

        #pragma unroll
        for (int ks = 0; ks < 8; ks++) {
            uint32_t ah[4], al[4];
            ldsm4(ah, sb + SM_QH + aoff + ks * 32);
            ldsm4(al, sb + SM_QL + aoff + ks * 32);
            #pragma unroll
            for (int np = 0; np < 4; np++) {
                uint32_t bf[4];
                ldsm4(bf, sb + SM_K + boff + np * (16 * FSTR) + ks * 32);
                mma_f16(s[np * 2],     ah, bf);
                mma_f16(s[np * 2],     al, bf);
                mma_f16(s[np * 2 + 1], ah, bf + 2);
                mma_f16(s[np * 2 + 1], al, bf + 2);
            }
        }

        // causal mask on diagonal tile
        const int rg0 = q0 + warp * 16 + (lane >> 2);
        if (kt == qt) {
            #pragma unroll
            for (int nt = 0; nt < 8; nt++) {
                int colb = k0 + nt * 8 + 2 * (lane & 3);
                #pragma unroll
                for (int e = 0; e < 4; e++) {
                    int col = colb + (e & 1);
                    int row = rg0 + ((e >> 1) ? 8 : 0);
                    if (col > row) s[nt][e] = -1e30f;
                }
            }
        }

        // online softmax
        float mx0 = -1e30f, mx1 = -1e30f;
        #pragma unroll
        for (int nt = 0; nt < 8; nt++) {
            mx0 = fmaxf(mx0, fmaxf(s[nt][0], s[nt][1]));
            mx1 = fmaxf(mx1, fmaxf(s[nt][2], s[nt][3]));
        }
        mx0 = fmaxf(mx0, __shfl_xor_sync(0xffffffffu, mx0, 1));
        mx0 = fmaxf(mx0, __shfl_xor_sync(0xffffffffu, mx0, 2));
        mx1 = fmaxf(mx1, __shfl_xor_sync(0xffffffffu, mx1, 1));
        mx1 = fmaxf(mx1, __shfl_xor_sync(0xffffffffu, mx1, 2));

        float mn0 = fmaxf(m0v, mx0);
        float mn1 = fmaxf(m1v, mx1);
        float al0 = __expf(m0v - mn0);
        float al1 = __expf(m1v - mn1);
        m0v = mn0; m1v = mn1;

        float sum0 = 0.f, sum1 = 0.f;
        #pragma unroll
        for (int nt = 0; nt < 8; nt++) {
            float p0 = __expf(s[nt][0] - mn0);
            float p1 = __expf(s[nt][1] - mn0);
            float p2 = __expf(s[nt][2] - mn1);
            float p3 = __expf(s[nt][3] - mn1);
            s[nt][0] = p0; s[nt][1] = p1; s[nt][2] = p2; s[nt][3] = p3;
            sum0 += p0 + p1;
            sum1 += p2 + p3;
        }
        sum0 += __shfl_xor_sync(0xffffffffu, sum0, 1);
        sum0 += __shfl_xor_sync(0xffffffffu, sum0, 2);
        sum1 += __shfl_xor_sync(0xffffffffu, sum1, 1);
        sum1 += __shfl_xor_sync(0xffffffffu, sum1, 2);
        l0 = l0 * al0 + sum0;
        l1 = l1 * al1 + sum1;

        #pragma unroll
        for (int t = 0; t < 16; t++) {
            oacc[t][0] *= al0; oacc[t][1] *= al0;
            oacc[t][2] *= al1; oacc[t][3] *= al1;
        }

        // O += (Ph+Pl) V
        #pragma unroll
        for (int kc = 0; kc < 4; kc++) {
            uint32_t pah[4], pal[4];
            #pragma unroll
            for (int half = 0; half < 2; half++) {
                const int nt = 2 * kc + half;
                float p0 = s[nt][0], p1 = s[nt][1], p2 = s[nt][2], p3 = s[nt][3];
                __half h0 = __float2half_rn(p0);
                __half h1 = __float2half_rn(p1);
                __half h2 = __float2half_rn(p2);
                __half h3 = __float2half_rn(p3);
                pah[half * 2 + 0] = packh(__half2float(h0), __half2float(h1));
                pah[half * 2 + 1] = packh(__half2float(h2), __half2float(h3));
                pal[half * 2 + 0] = packh(p0 - __half2float(h0), p1 - __half2float(h1));
                pal[half * 2 + 1] = packh(p2 - __half2float(h2), p3 - __half2float(h3));
            }
            #pragma unroll
            for (int dc = 0; dc < 8; dc++) {
                uint32_t vf[4];
                ldsm4t(vf, sb + SM_V + voff + kc * (16 * FSTR) + dc * 32);
                mma_f16(oacc[dc * 2],     pah, vf);
                mma_f16(oacc[dc * 2],     pal, vf);
                mma_f16(oacc[dc * 2 + 1], pah, vf + 2);
                mma_f16(oacc[dc * 2 + 1], pal, vf + 2);
            }
        }
        __syncthreads();
    }

    // normalize, split to fp16 hi/lo, write
    const float il0 = 1.f / l0;
    const float il1 = 1.f / l1;
    const int rowg = b * SEQ + q0 + warp * 16 + (lane >> 2);
    const int colg = h * HD + (lane & 3) * 2;
    #pragma unroll
    for (int nt = 0; nt < 16; nt++) {
        float y0 = oacc[nt][0] * il0, y1 = oacc[nt][1] * il0;
        float z0 = oacc[nt][2] * il1, z1 = oacc[nt][3] * il1;
        __half h0 = __float2half_rn(y0), h1 = __float2half_rn(y1);
        __half g0 = __float2half_rn(z0), g1 = __float2half_rn(z1);
        size_t o0 = (size_t)rowg * CDIM + colg + nt * 8;
        size_t o1 = (size_t)(rowg + 8) * CDIM + colg + nt * 8;
        *(__half2*)&oh[o0] = __halves2half2(h0, h1);
        *(__half2*)&oh[o1] = __halves2half2(g0, g1);
        *(__half2*)&ol[o0] = __halves2half2(
            __float2half_rn(y0 - __half2float(h0)),
            __float2half_rn(y1 - __half2float(h1)));
        *(__half2*)&ol[o1] = __halves2half2(
            __float2half_rn(z0 - __half2float(g0)),
            __float2half_rn(z1 - __half2float(g1)));
    }
}

// ---------------------------------------------------------------------------
extern "C" void kernel_launch(void* const* d_in, const int* in_sizes, int n_in,
                              void* d_out, int out_size) {
    const float* x   = (const float*)d_in[0];
    const int*   pid = (const int*)d_in[1];
    const float* Wq  = (const float*)d_in[2];
    const float* bq  = (const float*)d_in[3];
    const float* Wk  = (const float*)d_in[4];
    const float* bk  = (const float*)d_in[5];
    const float* Wv  = (const float*)d_in[6];
    const float* bv  = (const float*)d_in[7];
    const float* Wo  = (const float*)d_in[8];
    float* out = (float*)d_out;

    __half *xh, *xl, *wqkv, *wo, *qh, *ql, *kh, *vh, *oh, *ol;
    float2* cs;
    cudaGetSymbolAddress((void**)&xh, g_xh);
    cudaGetSymbolAddress((void**)&xl, g_xl);
    cudaGetSymbolAddress((void**)&wqkv, g_wqkv);
    cudaGetSymbolAddress((void**)&wo, g_wo);
    cudaGetSymbolAddress((void**)&qh, g_qh);
    cudaGetSymbolAddress((void**)&ql, g_ql);
    cudaGetSymbolAddress((void**)&kh, g_kh);
    cudaGetSymbolAddress((void**)&vh, g_vh);
    cudaGetSymbolAddress((void**)&oh, g_oh);
    cudaGetSymbolAddress((void**)&ol, g_ol);
    cudaGetSymbolAddress((void**)&cs, g_cs);

    const int M = BATCH * SEQ;   // 4096

    // prep
    build_cs<<<(SEQ * 64 + 255) / 256, 256>>>(cs);
    int nx = M * CDIM;
    split_x<<<(nx + 255) / 256, 256>>>(x, xh, xl, nx);
    transpose_f16<<<dim3(CDIM / 32, CDIM / 32), 256>>>(Wq, wqkv, CDIM, CDIM, 0);
    transpose_f16<<<dim3(KVC / 32,  CDIM / 32), 256>>>(Wk, wqkv, CDIM, KVC, CDIM);
    transpose_f16<<<dim3(KVC / 32,  CDIM / 32), 256>>>(Wv, wqkv, CDIM, KVC, CDIM + KVC);
    transpose_f16<<<dim3(CDIM / 32, CDIM / 32), 256>>>(Wo, wo, CDIM, CDIM, 0);

    // fused QKV projection + bias + RoPE + split
    cudaFuncSetAttribute(gemm_qkv, cudaFuncAttributeMaxDynamicSharedMemorySize, GSMEM);
    gemm_qkv<<<dim3(NQKV / GBN, M / GBM), 256, GSMEM>>>(
        xh, xl, wqkv, bq, bk, bv, pid, cs, qh, ql, kh, vh);

    // flash attention (fp16 2-term), writes split output
    cudaFuncSetAttribute(flash_attn_f16, cudaFuncAttributeMaxDynamicSharedMemorySize, FSMEM);
    flash_attn_f16<<<dim3(SEQ / 64, BATCH * NH), 128, FSMEM>>>(
        qh, ql, kh, vh, oh, ol);

    // output projection straight to d_out
    cudaFuncSetAttribute(gemm_out, cudaFuncAttributeMaxDynamicSharedMemorySize, GSMEM);
    gemm_out<<<dim3(CDIM / GBN, M / GBM), 256, GSMEM>>>(oh, ol, wo, out);
}